// round 15
// baseline (speedup 1.0000x reference)
#include <cuda_runtime.h>
#include <cuda_bf16.h>
#include <math.h>
#include <stdint.h>

#define PI_D 3.14159265358979323846

// ================= family-safe PTX helpers =================
__device__ __forceinline__ uint32_t smem_u32(const void* p) {
    uint32_t a;
    asm("{ .reg .u64 t; cvta.to.shared.u64 t, %1; cvt.u32.u64 %0, t; }" : "=r"(a) : "l"(p));
    return a;
}
__device__ __forceinline__ void cp_async16(uint32_t dst, const void* src) {
    asm volatile("cp.async.cg.shared.global [%0], [%1], 16;" :: "r"(dst), "l"(src) : "memory");
}
__device__ __forceinline__ void cp_commit() {
    asm volatile("cp.async.commit_group;" ::: "memory");
}
template <int N>
__device__ __forceinline__ void cp_wait() {
    asm volatile("cp.async.wait_group %0;" :: "n"(N) : "memory");
}
__device__ __forceinline__ void ldsm_x4(uint32_t& r0, uint32_t& r1, uint32_t& r2, uint32_t& r3,
                                        uint32_t addr) {
    asm volatile("ldmatrix.sync.aligned.m8n8.x4.shared.b16 {%0,%1,%2,%3}, [%4];"
                 : "=r"(r0), "=r"(r1), "=r"(r2), "=r"(r3) : "r"(addr));
}
__device__ __forceinline__ void mma_bf16(float* c, const uint32_t* a, const uint32_t* b) {
    asm volatile("mma.sync.aligned.m16n8k16.row.col.f32.bf16.bf16.f32 "
                 "{%0,%1,%2,%3}, {%4,%5,%6,%7}, {%8,%9}, {%0,%1,%2,%3};"
                 : "+f"(c[0]), "+f"(c[1]), "+f"(c[2]), "+f"(c[3])
                 : "r"(a[0]), "r"(a[1]), "r"(a[2]), "r"(a[3]), "r"(b[0]), "r"(b[1]));
}

// ================= global scratch =================
__device__ float g_dmat[5 * 19 * 81];

__device__ float g_psi0[32 * 64 * 165];
__device__ float g_psi1[64 * 128 * 165];
__device__ float g_psi2[128 * 128 * 9];
__device__ float g_part[12582912];  // split-K partials: 16*192*4096 = 8*192*8192 floats

__device__ __align__(256) __nv_bfloat16 g_Bf_h[4096 * 192];
__device__ __align__(256) __nv_bfloat16 g_Bf_l[4096 * 192];
__device__ __align__(256) __nv_bfloat16 g_Bb_h[192 * 4096];
__device__ __align__(256) __nv_bfloat16 g_Bb_l[192 * 4096];
__device__ __align__(256) __nv_bfloat16 g_y1h[4096 * 192];
__device__ __align__(256) __nv_bfloat16 g_y1l[4096 * 192];
__device__ __align__(256) __nv_bfloat16 g_y2h[8192 * 192];
__device__ __align__(256) __nv_bfloat16 g_y2l[8192 * 192];
__device__ __align__(256) __nv_bfloat16 g_sh[8192 * 4096];
__device__ __align__(256) __nv_bfloat16 g_sl[8192 * 4096];

// per-l GEMM operand arenas
__device__ __align__(256) __nv_bfloat16 g_gAh[675840];
__device__ __align__(256) __nv_bfloat16 g_gAl[675840];
__device__ __align__(256) __nv_bfloat16 g_gBh[1351680];
__device__ __align__(256) __nv_bfloat16 g_gBl[1351680];

// split weight operands
__device__ __align__(256) __nv_bfloat16 g_w0h[393216],  g_w0l[393216];
__device__ __align__(256) __nv_bfloat16 g_w1h[1572864], g_w1l[1572864];
__device__ __align__(256) __nv_bfloat16 g_wlh[524288],  g_wll[524288];
__device__ __align__(256) __nv_bfloat16 g_DKTh[36864],  g_DKTl[36864];
__device__ __align__(256) __nv_bfloat16 g_YSTh[2048],   g_YSTl[2048];

__device__ __forceinline__ void split32(float v, __nv_bfloat16& h, __nv_bfloat16& l) {
    h = __float2bfloat16(v);
    l = __float2bfloat16(v - __bfloat162float(h));
}
__device__ __forceinline__ int off165_of(int l) {
    return (l == 0) ? 0 : (l == 1) ? 1 : (l == 2) ? 10 : (l == 3) ? 35 : 84;
}

// ---------- d(beta) = exp(beta * X0_l): 95 warp jobs ----------
__global__ void k_expm()
{
    __shared__ float ws[16][729];
    const int wid_in = threadIdx.x >> 5;
    const int lane   = threadIdx.x & 31;
    const int w = blockIdx.x * 16 + wid_in;
    if (w >= 95) return;
    const int l = w / 19, bidx = w % 19;
    const int d = 2 * l + 1;

    float* Qre  = ws[wid_in];
    float* Qim  = Qre + 81;
    float* Amat = Qim + 81;
    float* Tre  = Amat + 81;
    float* Tim  = Tre + 81;
    float* Xm   = Tim + 81;
    float* Em   = Xm + 81;
    float* Pm   = Em + 81;
    float* tm   = Pm + 81;

    for (int e = lane; e < 243; e += 32) Qre[e] = 0.f;
    __syncwarp();

    if (lane == 0) {
        const float inv = 0.7071067811865476f;
        for (int m = 1; m <= l; m++) {
            Qre[(l - m) * d + (l + m)] = inv;
            Qim[(l - m) * d + (l - m)] = -inv;
            float sgn = (m & 1) ? -inv : inv;
            Qre[(l + m) * d + (l + m)] = sgn;
            Qim[(l + m) * d + (l - m)] = sgn;
        }
        Qre[l * d + l] = 1.f;
        for (int i2 = 0; i2 < d - 1; i2++) {
            float mm = (float)(-l + i2);
            float c  = 0.5f * sqrtf((float)(l * (l + 1)) - mm * (mm + 1.f));
            Amat[i2 * d + i2 + 1]   =  c;
            Amat[(i2 + 1) * d + i2] = -c;
        }
    }
    __syncwarp();

    for (int e = lane; e < d * d; e += 32) {
        int i = e / d, j = e % d;
        float sr = 0.f, si = 0.f;
        for (int k = 0; k < d; k++) {
            float a = Amat[k * d + j];
            sr += Qre[k * d + i] * a;
            si -= Qim[k * d + i] * a;
        }
        Tre[e] = sr; Tim[e] = si;
    }
    __syncwarp();

    double beta_d = (bidx < 16) ? ((bidx + 0.5) * PI_D / 16.0)
                                : ((double)(bidx - 15) * PI_D / 24.0);
    float beta = (float)beta_d;

    for (int e = lane; e < d * d; e += 32) {
        int i = e / d, j = e % d;
        float s = 0.f;
        for (int k = 0; k < d; k++)
            s += Tre[i * d + k] * Qre[k * d + j] - Tim[i * d + k] * Qim[k * d + j];
        Xm[e] = s * beta;
    }
    __syncwarp();

    float nrm = 0.f;
    for (int i = 0; i < d; i++) {
        float rs = 0.f;
        for (int j = 0; j < d; j++) rs += fabsf(Xm[i * d + j]);
        nrm = fmaxf(nrm, rs);
    }
    int sexp = 0;
    while (nrm > 0.5f) { nrm *= 0.5f; sexp++; }
    float sc = ldexpf(1.f, -sexp);
    for (int e = lane; e < d * d; e += 32) Xm[e] *= sc;
    __syncwarp();

    for (int e = lane; e < d * d; e += 32) {
        int i = e / d, j = e % d;
        Em[e] = Xm[e] + (i == j ? 1.f : 0.f);
        Pm[e] = Xm[e];
    }
    __syncwarp();
    for (int t = 2; t <= 10; t++) {
        float rt = 1.f / (float)t;
        for (int e = lane; e < d * d; e += 32) {
            int i = e / d, j = e % d;
            float s = 0.f;
            for (int k = 0; k < d; k++) s += Pm[i * d + k] * Xm[k * d + j];
            tm[e] = s * rt;
        }
        __syncwarp();
        for (int e = lane; e < d * d; e += 32) { Pm[e] = tm[e]; Em[e] += tm[e]; }
        __syncwarp();
    }
    for (int it = 0; it < sexp; it++) {
        for (int e = lane; e < d * d; e += 32) {
            int i = e / d, j = e % d;
            float s = 0.f;
            for (int k = 0; k < d; k++) s += Em[i * d + k] * Em[k * d + j];
            tm[e] = s;
        }
        __syncwarp();
        for (int e = lane; e < d * d; e += 32) Em[e] = tm[e];
        __syncwarp();
    }
    for (int e = lane; e < d * d; e += 32)
        g_dmat[(l * 19 + bidx) * 81 + e] = Em[e];
}

__device__ __forceinline__ float wig_elem(const float* __restrict__ dm, int l, int d,
                                          int u, int v, float alpha, float gamma)
{
    int mp = u - l, m = v - l;
    int r1, r2 = -1; float c1, c2 = 0.f;
    if (mp == 0) { r1 = l; c1 = 1.f; }
    else {
        int mu = mp > 0 ? mp : -mp;
        float sn, cs; sincosf((float)mu * alpha, &sn, &cs);
        if (mp > 0) { r1 = l + mu; c1 = cs; r2 = l - mu; c2 = -sn; }
        else        { r1 = l - mu; c1 = cs; r2 = l + mu; c2 =  sn; }
    }
    int k1, k2 = -1; float e1, e2 = 0.f;
    if (m == 0) { k1 = l; e1 = 1.f; }
    else {
        int mu = m > 0 ? m : -m;
        float sn, cs; sincosf((float)mu * gamma, &sn, &cs);
        if (m > 0) { k1 = l + mu; e1 = cs; k2 = l - mu; e2 =  sn; }
        else       { k1 = l - mu; e1 = cs; k2 = l + mu; e2 = -sn; }
    }
    float val = c1 * e1 * dm[r1 * d + k1];
    if (k2 >= 0) val += c1 * e2 * dm[r1 * d + k2];
    if (r2 >= 0) {
        val += c2 * e1 * dm[r2 * d + k1];
        if (k2 >= 0) val += c2 * e2 * dm[r2 * d + k2];
    }
    return val;
}

__device__ __forceinline__ void decode_l165(int i, int& l, int& off)
{
    if (i < 1)       { l = 0; off = 0; }
    else if (i < 10) { l = 1; off = 1; }
    else if (i < 35) { l = 2; off = 10; }
    else if (i < 84) { l = 3; off = 35; }
    else             { l = 4; off = 84; }
}

// DK^T split: DKT[i (0..191), k (0..191)] = DK[k,i]/192
__global__ void k_build_DK()
{
    int n = blockIdx.x;
    int i = threadIdx.x;
    float val = 0.f;
    if (i < 165) {
        int ia = n / 24, ib = (n % 24) / 8, ic = n % 8;
        double alpha = ia * (2.0 * PI_D / 8.0);
        double gam   = (-2.0 * PI_D + ic * (4.0 * PI_D / 7.0)) - alpha;
        int l, off; decode_l165(i, l, off);
        int d = 2 * l + 1, r = i - off, u = r / d, v = r % d;
        const float* dm = &g_dmat[(l * 19 + 16 + ib) * 81];
        val = wig_elem(dm, l, d, u, v, (float)alpha, (float)gam)
            * sqrtf(2.f * l + 1.f) * (1.f / 192.f);
    }
    __nv_bfloat16 h, lo;
    split32(val, h, lo);
    g_DKTh[i * 192 + n] = h;
    g_DKTl[i * 192 + n] = lo;
}

// split-bf16 D_ACT operands, smem-staged (one block per (ia, ib))
__global__ void __launch_bounds__(256) k_build_DACT()
{
    __shared__ float sval[16][166];
    const int ia = blockIdx.x >> 4, ib = blockIdx.x & 15;
    const int n0 = blockIdx.x * 16;
    const int tid = threadIdx.x;

    for (int idx = tid; idx < 16 * 165; idx += 256) {
        int ic = idx / 165, i = idx - ic * 165;
        float alpha = (float)(ia * (2.0 * PI_D / 16.0));
        float gam   = (float)(ic * (2.0 * PI_D / 16.0));
        int l, off; decode_l165(i, l, off);
        int d = 2 * l + 1, r = i - off, u = r / d, v = r % d;
        const float* dm = &g_dmat[(l * 19 + ib) * 81];
        sval[ic][i] = wig_elem(dm, l, d, u, v, alpha, gam) * sqrtf(2.f * l + 1.f);
    }
    __syncthreads();

    for (int idx = tid; idx < 16 * 192; idx += 256) {
        int ic = idx / 192, i = idx - ic * 192;
        float v = (i < 165) ? sval[ic][i] : 0.f;
        __nv_bfloat16 h, lo;
        split32(v, h, lo);
        size_t o = (size_t)(n0 + ic) * 192 + i;
        g_Bf_h[o] = h; g_Bf_l[o] = lo;
    }
    float bb = (float)((ib + 0.5) * PI_D / 16.0);
    float qw = sinf(bb) * (float)(0.09801714032956060362 / 256.0); // sin(pi/32)/256
    for (int idx = tid; idx < 192 * 16; idx += 256) {
        int i = idx >> 4, ic = idx & 15;
        float v = (i < 165) ? sval[ic][i] * qw : 0.f;
        __nv_bfloat16 h, lo;
        split32(v, h, lo);
        size_t o = (size_t)i * 4096 + n0 + ic;
        g_Bb_h[o] = h; g_Bb_l[o] = lo;
    }
}

// Y_S2^T split: YST[i (0..63), k (0..31)] = YS2[k, i]/24 (i<9, k<24), else 0
__global__ void k_build_YS2()
{
    __shared__ float sY[24][9];
    int t = threadIdx.x;
    if (t < 216) {
        int p = t / 9, i = t % 9;
        int ia = p / 3, ib = p % 3;
        float alpha = (float)(ia * (2.0 * PI_D / 8.0));
        int l, off;
        if (i < 1)      { l = 0; off = 0; }
        else if (i < 4) { l = 1; off = 1; }
        else            { l = 2; off = 4; }
        int d = 2 * l + 1, u = i - off, mp = u - l;
        const float* dm = &g_dmat[(l * 19 + 16 + ib) * 81];
        float val;
        if (mp == 0) val = dm[l * d + l];
        else {
            int mu = mp > 0 ? mp : -mp;
            float sn, cs; sincosf((float)mu * alpha, &sn, &cs);
            if (mp > 0) val = cs * dm[(l + mu) * d + l] - sn * dm[(l - mu) * d + l];
            else        val = cs * dm[(l - mu) * d + l] + sn * dm[(l + mu) * d + l];
        }
        sY[p][i] = val * sqrtf(2.f * l + 1.f) * (1.f / 24.f);
    }
    __syncthreads();
    for (int idx = t; idx < 64 * 32; idx += blockDim.x) {
        int i = idx >> 5, k = idx & 31;
        float v = (i < 9 && k < 24) ? sY[k][i] : 0.f;
        __nv_bfloat16 h, lo;
        split32(v, h, lo);
        g_YSTh[idx] = h; g_YSTl[idx] = lo;
    }
}

// ---------- elementwise splits ----------
__global__ void k_split(const float* __restrict__ in,
                        __nv_bfloat16* __restrict__ oh, __nv_bfloat16* __restrict__ ol, int n)
{
    int i = blockIdx.x * 256 + threadIdx.x;
    if (i >= n) return;
    __nv_bfloat16 h, lo;
    split32(in[i], h, lo);
    oh[i] = h; ol[i] = lo;
}
__global__ void k_split_pad(const float* __restrict__ in,
                            __nv_bfloat16* __restrict__ oh, __nv_bfloat16* __restrict__ ol,
                            int n)
{
    int i = blockIdx.x * 256 + threadIdx.x;
    if (i >= n) return;
    int r = i >> 5, c = i & 31;
    float v = (c < 24) ? in[r * 24 + c] : 0.f;
    __nv_bfloat16 h, lo;
    split32(v, h, lo);
    oh[i] = h; ol[i] = lo;
}

// ---------- gathers for per-l block-diagonal GEMMs ----------
__global__ void k_gather_A(const float* __restrict__ X,
                           __nv_bfloat16* __restrict__ Ah, __nv_bfloat16* __restrict__ Al,
                           int f_in, int rowlen, int total)
{
    int e = blockIdx.x * 256 + threadIdx.x;
    if (e >= total) return;
    const int sa = 64 * f_in;
    int l, off;
    if      (e < sa * 1)  { l = 0; off = 0; }
    else if (e < sa * 10) { l = 1; off = 1; }
    else if (e < sa * 35) { l = 2; off = 10; }
    else if (e < sa * 84) { l = 3; off = 35; }
    else                  { l = 4; off = 84; }
    const int d = 2 * l + 1;
    const int Kl = f_in * d;
    int local = e - sa * off;
    int r = local / Kl, c = local - r * Kl;
    int b = r / d, m = r - b * d;
    int x = c / d, u = c - x * d;
    float v = X[(size_t)(b * f_in + x) * rowlen + off + u * d + m];
    __nv_bfloat16 h, lo;
    split32(v, h, lo);
    Ah[e] = h; Al[e] = lo;
}

__global__ void k_gather_B(const float* __restrict__ PSI,
                           __nv_bfloat16* __restrict__ Bh, __nv_bfloat16* __restrict__ Bl,
                           int f_in, int f_out, int total)
{
    int e = blockIdx.x * 256 + threadIdx.x;
    if (e >= total) return;
    const int sb = f_in * f_out;
    int l, off;
    if      (e < sb * 1)  { l = 0; off = 0; }
    else if (e < sb * 10) { l = 1; off = 1; }
    else if (e < sb * 35) { l = 2; off = 10; }
    else if (e < sb * 84) { l = 3; off = 35; }
    else                  { l = 4; off = 84; }
    const int d = 2 * l + 1;
    const int Kl = f_in * d;
    int local = e - sb * off;
    int r = local / Kl, c = local - r * Kl;
    int y = r / d, v = r - y * d;
    int x = c / d, u = c - x * d;
    float val = PSI[(size_t)(x * f_out + y) * 165 + off + u * d + v];
    __nv_bfloat16 h, lo;
    split32(val, h, lo);
    Bh[e] = h; Bl[e] = lo;
}

// B for so3->s2: B2[y, (x*d+u)] = psi2[(x*128+y)*9 + offY + u], l in {0,1,2}
__global__ void k_gather_B2(const float* __restrict__ PSI2,
                            __nv_bfloat16* __restrict__ Bh, __nv_bfloat16* __restrict__ Bl,
                            int total)
{
    int e = blockIdx.x * 256 + threadIdx.x;
    if (e >= total) return;
    const int sb = 16384; // 128*128
    int l, offY;
    if      (e < sb * 1) { l = 0; offY = 0; }
    else if (e < sb * 4) { l = 1; offY = 1; }
    else                 { l = 2; offY = 4; }
    const int d = 2 * l + 1;
    const int Kl = 128 * d;
    int local = e - sb * offY;
    int y = local / Kl, c = local - y * Kl;
    int x = c / d, u = c - x * d;
    float val = PSI2[(size_t)(x * 128 + y) * 9 + offY + u];
    __nv_bfloat16 h, lo;
    split32(val, h, lo);
    Bh[e] = h; Bl[e] = lo;
}

__global__ void k_zero_pad(__nv_bfloat16* __restrict__ Yh, __nv_bfloat16* __restrict__ Yl,
                           int rows)
{
    int idx = blockIdx.x * 256 + threadIdx.x;
    int total = rows * 27;
    if (idx >= total) return;
    int r = idx / 27, c = 165 + idx - r * 27;
    __nv_bfloat16 z = __float2bfloat16(0.f);
    Yh[(size_t)r * 192 + c] = z;
    Yl[(size_t)r * 192 + c] = z;
}

// fused split-K reduction + gather_A: sums transposed partials and scatters
// split-bf16 directly into the per-l arena.
// part[(s*192 + c)*M + m]; e = 64*f_in*off + (b*d+mm)*(f_in*d) + x*d + u
__global__ void k_reduce_g(const float* __restrict__ part,
                           __nv_bfloat16* __restrict__ Ah, __nv_bfloat16* __restrict__ Al,
                           int M, int S, int f_in, int cmax)
{
    int idx = blockIdx.x * 256 + threadIdx.x;
    if (idx >= M * 165) return;
    int m = idx & (M - 1);
    int c = idx >> (M == 4096 ? 12 : 13);
    if (c >= cmax) return;
    float acc = 0.f;
    for (int s = 0; s < S; s++)
        acc += part[((size_t)s * 192 + c) * M + m];
    int l, off; decode_l165(c, l, off);
    int d = 2 * l + 1;
    int u = (c - off) / d, mm = (c - off) - u * d;
    int b = m / f_in, x = m - b * f_in;
    size_t e = (size_t)64 * f_in * off + (size_t)(b * d + mm) * (f_in * d) + x * d + u;
    __nv_bfloat16 h, lo;
    split32(acc, h, lo);
    Ah[e] = h; Al[e] = lo;
}

// ---------- shared HMMA split-bf16 mainloop ----------
template <int BM, int BN, int WM, int WN>
__device__ __forceinline__ void mma_mainloop(
    const __nv_bfloat16* __restrict__ Ahi, const __nv_bfloat16* __restrict__ Alo,
    const __nv_bfloat16* __restrict__ Bhi, const __nv_bfloat16* __restrict__ Blo,
    int row0, int n0, int lda, int Kloop, char* smem,
    float acc[WM / 16][WN / 8][4])
{
    constexpr int MT = WM / 16, NT = WN / 8;
    constexpr int SA = BM * 80, SB = BN * 80;
    constexpr int SS = 2 * SA + 2 * SB;
    const uint32_t sbase = smem_u32(smem);
    const int tid  = threadIdx.x;
    const int lane = tid & 31, wid = tid >> 5;
    const int m_warp = (wid >> 2) * WM, n_warp = (wid & 3) * WN;
    const int NKB = Kloop >> 5;

    auto load_stage = [&](int kb, int s) {
        const uint32_t sbs = sbase + s * SS;
#pragma unroll
        for (int i = tid; i < BM * 8; i += 256) {
            int mtx = (i >= BM * 4);
            int j = i - mtx * (BM * 4);
            int r = j >> 2, c = j & 3;
            const __nv_bfloat16* src = (mtx ? Alo : Ahi)
                + (size_t)(row0 + r) * lda + kb * 32 + c * 8;
            cp_async16(sbs + mtx * SA + r * 80 + c * 16, src);
        }
#pragma unroll
        for (int i = tid; i < BN * 8; i += 256) {
            int mtx = (i >= BN * 4);
            int j = i - mtx * (BN * 4);
            int r = j >> 2, c = j & 3;
            const __nv_bfloat16* src = (mtx ? Blo : Bhi)
                + (size_t)(n0 + r) * lda + kb * 32 + c * 8;
            cp_async16(sbs + 2 * SA + mtx * SB + r * 80 + c * 16, src);
        }
    };

    load_stage(0, 0); cp_commit();
    if (NKB > 1) load_stage(1, 1);
    cp_commit();

    const int a_roff = (lane & 7) + ((lane >> 3) & 1) * 8;
    const int a_coff = ((lane >> 4) & 1) * 8;
    const int b_roff = (lane & 7) + ((lane >> 4) & 1) * 8;
    const int b_coff = ((lane >> 3) & 1) * 8;

    for (int kb = 0; kb < NKB; kb++) {
        if (kb + 1 < NKB) cp_wait<1>(); else cp_wait<0>();
        __syncthreads();
        const uint32_t sbs = sbase + (kb & 1) * SS;
#pragma unroll
        for (int kk = 0; kk < 2; kk++) {
            uint32_t bh[NT][2], bl[NT][2];
#pragma unroll
            for (int n2 = 0; n2 < NT / 2; n2++) {
                uint32_t ab = sbs + 2 * SA
                    + (n_warp + n2 * 16 + b_roff) * 80 + (kk * 16 + b_coff) * 2;
                ldsm_x4(bh[2 * n2][0], bh[2 * n2][1], bh[2 * n2 + 1][0], bh[2 * n2 + 1][1], ab);
                ldsm_x4(bl[2 * n2][0], bl[2 * n2][1], bl[2 * n2 + 1][0], bl[2 * n2 + 1][1],
                        ab + SB);
            }
            uint32_t af[MT][4];
#pragma unroll
            for (int mt = 0; mt < MT; mt++) {
                uint32_t aa = sbs + (m_warp + mt * 16 + a_roff) * 80 + (kk * 16 + a_coff) * 2;
                ldsm_x4(af[mt][0], af[mt][1], af[mt][2], af[mt][3], aa);
            }
#pragma unroll
            for (int mt = 0; mt < MT; mt++)
#pragma unroll
                for (int nt = 0; nt < NT; nt++) mma_bf16(acc[mt][nt], af[mt], bh[nt]);
#pragma unroll
            for (int mt = 0; mt < MT; mt++)
#pragma unroll
                for (int nt = 0; nt < NT; nt++) mma_bf16(acc[mt][nt], af[mt], bl[nt]);
#pragma unroll
            for (int mt = 0; mt < MT; mt++) {
                uint32_t aa = sbs + SA
                    + (m_warp + mt * 16 + a_roff) * 80 + (kk * 16 + a_coff) * 2;
                ldsm_x4(af[mt][0], af[mt][1], af[mt][2], af[mt][3], aa);
            }
#pragma unroll
            for (int mt = 0; mt < MT; mt++)
#pragma unroll
                for (int nt = 0; nt < NT; nt++) mma_bf16(acc[mt][nt], af[mt], bh[nt]);
        }
        __syncthreads();
        if (kb + 2 < NKB) load_stage(kb + 2, kb & 1);
        cp_commit();
    }
    cp_wait<0>();
    __syncthreads();
}

// ---------- fwd act GEMM: relu + split-bf16 store ----------
__global__ void __launch_bounds__(256)
k_mma_relu(const __nv_bfloat16* __restrict__ Ahi, const __nv_bfloat16* __restrict__ Alo,
           const __nv_bfloat16* __restrict__ Bhi, const __nv_bfloat16* __restrict__ Blo,
           __nv_bfloat16* __restrict__ Chi, __nv_bfloat16* __restrict__ Clo, int K)
{
    constexpr int BM = 128, BN = 128, WM = 64, WN = 32, MT = 4, NT = 4;
    extern __shared__ char smem[];
    const int tid = threadIdx.x, lane = tid & 31, wid = tid >> 5;
    const int m_warp = (wid >> 2) * WM, n_warp = (wid & 3) * WN;
    const int row0 = blockIdx.y * BM, n0 = blockIdx.x * BN;
    float acc[MT][NT][4];
#pragma unroll
    for (int i = 0; i < MT; i++)
#pragma unroll
        for (int j = 0; j < NT; j++)
#pragma unroll
            for (int q = 0; q < 4; q++) acc[i][j][q] = 0.f;

    mma_mainloop<BM, BN, WM, WN>(Ahi, Alo, Bhi, Blo, row0, n0, K, K, smem, acc);

    const int qr = lane >> 2, qc = lane & 3;
    constexpr int LDS = BN + 8;
    __nv_bfloat16* sC = (__nv_bfloat16*)smem;
#pragma unroll
    for (int mt = 0; mt < MT; mt++)
#pragma unroll
        for (int nt = 0; nt < NT; nt++)
#pragma unroll
            for (int i = 0; i < 2; i++) {
                int r = m_warp + mt * 16 + qr + i * 8;
                int c = n_warp + nt * 8 + qc * 2;
                float v0 = acc[mt][nt][2 * i];
                float v1 = acc[mt][nt][2 * i + 1];
                v0 = v0 > 0.f ? v0 * 1.4142135623730951f : 0.f;
                v1 = v1 > 0.f ? v1 * 1.4142135623730951f : 0.f;
                __nv_bfloat162 hp;
                hp.x = __float2bfloat16(v0);
                hp.y = __float2bfloat16(v1);
                *(__nv_bfloat162*)&sC[r * LDS + c] = hp;
                acc[mt][nt][2 * i]     = v0 - __bfloat162float(hp.x);
                acc[mt][nt][2 * i + 1] = v1 - __bfloat162float(hp.y);
            }
    __syncthreads();
#pragma unroll
    for (int it = 0; it < BM * BN / 8 / 256; it++) {
        int idx = it * 256 + tid;
        int r = idx / (BN / 8), c8 = idx % (BN / 8);
        *(uint4*)&Chi[(size_t)(row0 + r) * 4096 + n0 + c8 * 8] = *(uint4*)&sC[r * LDS + c8 * 8];
    }
    __syncthreads();
#pragma unroll
    for (int mt = 0; mt < MT; mt++)
#pragma unroll
        for (int nt = 0; nt < NT; nt++)
#pragma unroll
            for (int i = 0; i < 2; i++) {
                int r = m_warp + mt * 16 + qr + i * 8;
                int c = n_warp + nt * 8 + qc * 2;
                __nv_bfloat162 lp;
                lp.x = __float2bfloat16(acc[mt][nt][2 * i]);
                lp.y = __float2bfloat16(acc[mt][nt][2 * i + 1]);
                *(__nv_bfloat162*)&sC[r * LDS + c] = lp;
            }
    __syncthreads();
#pragma unroll
    for (int it = 0; it < BM * BN / 8 / 256; it++) {
        int idx = it * 256 + tid;
        int r = idx / (BN / 8), c8 = idx % (BN / 8);
        *(uint4*)&Clo[(size_t)(row0 + r) * 4096 + n0 + c8 * 8] = *(uint4*)&sC[r * LDS + c8 * 8];
    }
}

// ---------- fp32-output GEMM (psi projections; 64x64) ----------
__global__ void __launch_bounds__(256)
k_mma_f32(const __nv_bfloat16* __restrict__ Ahi, const __nv_bfloat16* __restrict__ Alo,
          const __nv_bfloat16* __restrict__ Bhi, const __nv_bfloat16* __restrict__ Blo,
          float* __restrict__ Cf, int K, int ldc, int ncol)
{
    constexpr int BM = 64, BN = 64, WM = 32, WN = 16, MT = 2, NT = 2;
    extern __shared__ char smem[];
    const int tid = threadIdx.x, lane = tid & 31, wid = tid >> 5;
    const int m_warp = (wid >> 2) * WM, n_warp = (wid & 3) * WN;
    const int row0 = blockIdx.y * BM, n0 = blockIdx.x * BN;
    float acc[MT][NT][4];
#pragma unroll
    for (int i = 0; i < MT; i++)
#pragma unroll
        for (int j = 0; j < NT; j++)
#pragma unroll
            for (int q = 0; q < 4; q++) acc[i][j][q] = 0.f;

    mma_mainloop<BM, BN, WM, WN>(Ahi, Alo, Bhi, Blo, row0, n0, K, K, smem, acc);

    const int qr = lane >> 2, qc = lane & 3;
#pragma unroll
    for (int mt = 0; mt < MT; mt++)
#pragma unroll
        for (int nt = 0; nt < NT; nt++)
#pragma unroll
            for (int i = 0; i < 2; i++) {
                int r = row0 + m_warp + mt * 16 + qr + i * 8;
                int c = n0 + n_warp + nt * 8 + qc * 2;
                if (c < ncol)     Cf[(size_t)r * ldc + c]     = acc[mt][nt][2 * i];
                if (c + 1 < ncol) Cf[(size_t)r * ldc + c + 1] = acc[mt][nt][2 * i + 1];
            }
}

// ---------- transposed split-K bwd GEMM: Cpart[s][192][M] = Bb x s^T chunk ----------
// A = Bb [192, lda], B = s [Mtot, lda]. Tile 64x256, warps 2x4 (32x64 each).
__global__ void __launch_bounds__(256)
k_mma_f32t(const __nv_bfloat16* __restrict__ Ahi, const __nv_bfloat16* __restrict__ Alo,
           const __nv_bfloat16* __restrict__ Bhi, const __nv_bfloat16* __restrict__ Blo,
           float* __restrict__ Cpart, int lda, int Klen, int Mtot)
{
    constexpr int BM = 64, BN = 256, WM = 32, WN = 64, MT = 2, NT = 8;
    extern __shared__ char smem[];
    const int tid = threadIdx.x, lane = tid & 31, wid = tid >> 5;
    const int m_warp = (wid >> 2) * WM, n_warp = (wid & 3) * WN;
    const int row0 = blockIdx.y * BM, n0 = blockIdx.x * BN;
    const int s = blockIdx.z;
    const int k0 = s * Klen;
    float acc[MT][NT][4];
#pragma unroll
    for (int i = 0; i < MT; i++)
#pragma unroll
        for (int j = 0; j < NT; j++)
#pragma unroll
            for (int q = 0; q < 4; q++) acc[i][j][q] = 0.f;

    mma_mainloop<BM, BN, WM, WN>(Ahi + k0, Alo + k0, Bhi + k0, Blo + k0,
                                 row0, n0, lda, Klen, smem, acc);

    float* outp = Cpart + (size_t)s * 192 * Mtot;
    const int qr = lane >> 2, qc = lane & 3;
#pragma unroll
    for (int mt = 0; mt < MT; mt++)
#pragma unroll
        for (int nt = 0; nt < NT; nt++)
#pragma unroll
            for (int i = 0; i < 2; i++) {
                int rC = row0 + m_warp + mt * 16 + qr + i * 8;
                int cM = n0 + n_warp + nt * 8 + qc * 2;
                outp[(size_t)rC * Mtot + cM]     = acc[mt][nt][2 * i];
                outp[(size_t)rC * Mtot + cM + 1] = acc[mt][nt][2 * i + 1];
            }
}

// ---------- merged per-l so3_linear GEMM ----------
__global__ void __launch_bounds__(256)
k_mma_so3(const __nv_bfloat16* __restrict__ gAh, const __nv_bfloat16* __restrict__ gAl,
          const __nv_bfloat16* __restrict__ gBh, const __nv_bfloat16* __restrict__ gBl,
          __nv_bfloat16* __restrict__ Yh, __nv_bfloat16* __restrict__ Yl,
          int f_in, int f_out)
{
    constexpr int BM = 64, BN = 64, WM = 32, WN = 16, MT = 2, NT = 2;
    const int l = blockIdx.z;
    const int d = 2 * l + 1;
    const int off = off165_of(l);
    const int M = 64 * d, N = f_out * d, K = f_in * d;
    if ((int)blockIdx.x * BN >= N || (int)blockIdx.y * BM >= M) return;

    extern __shared__ char smem[];
    const int tid = threadIdx.x, lane = tid & 31, wid = tid >> 5;
    const int m_warp = (wid >> 2) * WM, n_warp = (wid & 3) * WN;
    const int row0 = blockIdx.y * BM, n0 = blockIdx.x * BN;
    const size_t oA = (size_t)64 * f_in * off;
    const size_t oB = (size_t)f_in * f_out * off;
    float acc[MT][NT][4];
#pragma unroll
    for (int i = 0; i < MT; i++)
#pragma unroll
        for (int j = 0; j < NT; j++)
#pragma unroll
            for (int q = 0; q < 4; q++) acc[i][j][q] = 0.f;

    mma_mainloop<BM, BN, WM, WN>(gAh + oA, gAl + oA, gBh + oB, gBl + oB,
                                 row0, n0, K, K, smem, acc);

    const float scale = rsqrtf((float)(f_in * d));
    const int qr = lane >> 2, qc = lane & 3;
#pragma unroll
    for (int mt = 0; mt < MT; mt++)
#pragma unroll
        for (int nt = 0; nt < NT; nt++)
#pragma unroll
            for (int i = 0; i < 2; i++) {
                int r = row0 + m_warp + mt * 16 + qr + i * 8;
                int b = r / d, m = r - b * d;
#pragma unroll
                for (int jj = 0; jj < 2; jj++) {
                    int c = n0 + n_warp + nt * 8 + qc * 2 + jj;
                    int y = c / d, v = c - y * d;
                    float val = acc[mt][nt][2 * i + jj] * scale;
                    __nv_bfloat16 h, lo;
                    split32(val, h, lo);
                    size_t o = (size_t)(b * f_out + y) * 192 + off + v * d + m;
                    Yh[o] = h; Yl[o] = lo;
                }
            }
}

// ---------- merged per-l so3 -> s2 GEMM (fp32 scatter to output) ----------
__global__ void __launch_bounds__(256)
k_mma_s2(const __nv_bfloat16* __restrict__ gAh, const __nv_bfloat16* __restrict__ gAl,
         const __nv_bfloat16* __restrict__ gBh, const __nv_bfloat16* __restrict__ gBl,
         float* __restrict__ O)
{
    constexpr int BM = 64, BN = 64, WM = 32, WN = 16, MT = 2, NT = 2;
    const int l = blockIdx.z;
    const int d = 2 * l + 1;
    const int offY = l * l;
    const int offA = (l == 0) ? 0 : (l == 1) ? 1 : 10;
    const int M = 64 * d, K = 128 * d;
    if ((int)blockIdx.y * BM >= M) return;

    extern __shared__ char smem[];
    const int tid = threadIdx.x, lane = tid & 31, wid = tid >> 5;
    const int m_warp = (wid >> 2) * WM, n_warp = (wid & 3) * WN;
    const int row0 = blockIdx.y * BM, n0 = blockIdx.x * BN;
    const size_t oA = (size_t)8192 * offA;
    const size_t oB = (size_t)16384 * offY;
    float acc[MT][NT][4];
#pragma unroll
    for (int i = 0; i < MT; i++)
#pragma unroll
        for (int j = 0; j < NT; j++)
#pragma unroll
            for (int q = 0; q < 4; q++) acc[i][j][q] = 0.f;

    mma_mainloop<BM, BN, WM, WN>(gAh + oA, gAl + oA, gBh + oB, gBl + oB,
                                 row0, n0, K, K, smem, acc);

    const float scale = rsqrtf(128.f * (float)d);
    const int qr = lane >> 2, qc = lane & 3;
#pragma unroll
    for (int mt = 0; mt < MT; mt++)
#pragma unroll
        for (int nt = 0; nt < NT; nt++)
#pragma unroll
            for (int i = 0; i < 2; i++) {
                int r = row0 + m_warp + mt * 16 + qr + i * 8;
                int b = r / d, m = r - b * d;
#pragma unroll
                for (int jj = 0; jj < 2; jj++) {
                    int y = n0 + n_warp + nt * 8 + qc * 2 + jj;
                    O[(size_t)(b * 128 + y) * 9 + offY + m] =
                        acc[mt][nt][2 * i + jj] * scale;
                }
            }
}

// ---------- launch ----------
extern "C" void kernel_launch(void* const* d_in, const int* in_sizes, int n_in,
                              void* d_out, int out_size)
{
    const float* x    = (const float*)d_in[0];
    const float* w0   = (const float*)d_in[1];
    const float* w1   = (const float*)d_in[2];
    const float* wlin = (const float*)d_in[3];
    float* out = (float*)d_out;

    float *psi0, *psi1, *psi2, *part;
    __nv_bfloat16 *Bfh, *Bfl, *Bbh, *Bbl, *y1h, *y1l, *y2h, *y2l, *sh, *sl;
    __nv_bfloat16 *gAh, *gAl, *gBh, *gBl;
    __nv_bfloat16 *w0h, *w0l, *w1h, *w1l, *wlh, *wll, *DKTh, *DKTl, *YSTh, *YSTl;
    cudaGetSymbolAddress((void**)&psi0, g_psi0);
    cudaGetSymbolAddress((void**)&psi1, g_psi1);
    cudaGetSymbolAddress((void**)&psi2, g_psi2);
    cudaGetSymbolAddress((void**)&part, g_part);
    cudaGetSymbolAddress((void**)&Bfh, g_Bf_h);
    cudaGetSymbolAddress((void**)&Bfl, g_Bf_l);
    cudaGetSymbolAddress((void**)&Bbh, g_Bb_h);
    cudaGetSymbolAddress((void**)&Bbl, g_Bb_l);
    cudaGetSymbolAddress((void**)&y1h, g_y1h);
    cudaGetSymbolAddress((void**)&y1l, g_y1l);
    cudaGetSymbolAddress((void**)&y2h, g_y2h);
    cudaGetSymbolAddress((void**)&y2l, g_y2l);
    cudaGetSymbolAddress((void**)&sh, g_sh);
    cudaGetSymbolAddress((void**)&sl, g_sl);
    cudaGetSymbolAddress((void**)&gAh, g_gAh);
    cudaGetSymbolAddress((void**)&gAl, g_gAl);
    cudaGetSymbolAddress((void**)&gBh, g_gBh);
    cudaGetSymbolAddress((void**)&gBl, g_gBl);
    cudaGetSymbolAddress((void**)&w0h, g_w0h);
    cudaGetSymbolAddress((void**)&w0l, g_w0l);
    cudaGetSymbolAddress((void**)&w1h, g_w1h);
    cudaGetSymbolAddress((void**)&w1l, g_w1l);
    cudaGetSymbolAddress((void**)&wlh, g_wlh);
    cudaGetSymbolAddress((void**)&wll, g_wll);
    cudaGetSymbolAddress((void**)&DKTh, g_DKTh);
    cudaGetSymbolAddress((void**)&DKTl, g_DKTl);
    cudaGetSymbolAddress((void**)&YSTh, g_YSTh);
    cudaGetSymbolAddress((void**)&YSTl, g_YSTl);

    constexpr int SMEMF = 2 * (2 * 128 * 80 + 2 * 128 * 80);  // 81920
    constexpr int SMEMB = 2 * (2 * 64 * 80 + 2 * 64 * 80);    // 40960
    constexpr int SMEMT = 2 * (2 * 64 * 80 + 2 * 256 * 80);   // 102400
    cudaFuncSetAttribute((const void*)k_mma_relu,
                         cudaFuncAttributeMaxDynamicSharedMemorySize, SMEMF);
    cudaFuncSetAttribute((const void*)k_mma_f32t,
                         cudaFuncAttributeMaxDynamicSharedMemorySize, SMEMT);

    // constants + psi (slot 5 = launch index 3 -> psi1 64x64 reference kernel)
    k_expm<<<6, 512>>>();                                                   // 0
    k_build_DK<<<192, 192>>>();                                             // 1
    k_split<<<(1572864 + 255) / 256, 256>>>(w1, w1h, w1l, 1572864);         // 2
    k_mma_f32<<<dim3(3, 128), 256, SMEMB>>>(w1h, w1l, DKTh, DKTl,
                                            psi1, 192, 165, 165);           // 3 <- profiled
    k_build_DACT<<<256, 256>>>();                                           // 4
    k_split<<<(393216 + 255) / 256, 256>>>(w0, w0h, w0l, 393216);           // 5
    k_mma_f32<<<dim3(3, 32), 256, SMEMB>>>(w0h, w0l, DKTh, DKTl,
                                           psi0, 192, 165, 165);            // 6
    k_build_YS2<<<1, 256>>>();                                              // 7
    k_split_pad<<<(524288 + 255) / 256, 256>>>(wlin, wlh, wll, 524288);     // 8
    k_mma_f32<<<dim3(1, 256), 256, SMEMB>>>(wlh, wll, YSTh, YSTl,
                                            psi2, 32, 9, 9);                // 9

    // ---- layer 0 ----
    k_gather_A<<<(2048 * 165 + 255) / 256, 256>>>(x, gAh, gAl, 32, 455, 2048 * 165);
    k_gather_B<<<(2048 * 165 + 255) / 256, 256>>>(psi0, gBh, gBl, 32, 64, 2048 * 165);
    k_mma_so3<<<dim3(9, 9, 5), 256, SMEMB>>>(gAh, gAl, gBh, gBl, y1h, y1l, 32, 64);
    k_zero_pad<<<(4096 * 27 + 255) / 256, 256>>>(y1h, y1l, 4096);
    k_mma_relu<<<dim3(32, 32), 256, SMEMF>>>(y1h, y1l, Bfh, Bfl, sh, sl, 192);
    // bwd0 transposed 64x256: split-K 16 x 256 -> 768 CTAs; fused reduce+gather
    k_mma_f32t<<<dim3(16, 3, 16), 256, SMEMT>>>(Bbh, Bbl, sh, sl, part, 4096, 256, 4096);
    k_reduce_g<<<(4096 * 165 + 255) / 256, 256>>>(part, gAh, gAl, 4096, 16, 64, 165);

    // ---- layer 1 ----
    k_gather_B<<<(8192 * 165 + 255) / 256, 256>>>(psi1, gBh, gBl, 64, 128, 8192 * 165);
    k_mma_so3<<<dim3(18, 9, 5), 256, SMEMB>>>(gAh, gAl, gBh, gBl, y2h, y2l, 64, 128);
    k_zero_pad<<<(8192 * 27 + 255) / 256, 256>>>(y2h, y2l, 8192);
    k_mma_relu<<<dim3(32, 64), 256, SMEMF>>>(y2h, y2l, Bfh, Bfl, sh, sl, 192);
    // bwd1 transposed 64x256: split-K 8 x 512 -> 768 CTAs; fused reduce+gather (l<=2)
    k_mma_f32t<<<dim3(32, 3, 8), 256, SMEMT>>>(Bbh, Bbl, sh, sl, part, 4096, 512, 8192);
    k_reduce_g<<<(8192 * 165 + 255) / 256, 256>>>(part, gAh, gAl, 8192, 8, 128, 35);

    // ---- final so3 -> s2 ----
    k_gather_B2<<<(16384 * 9 + 255) / 256, 256>>>(psi2, gBh, gBl, 16384 * 9);
    k_mma_s2<<<dim3(2, 5, 3), 256, SMEMB>>>(gAh, gAl, gBh, gBl, out);
}

// round 16
// speedup vs baseline: 1.2037x; 1.2037x over previous
#include <cuda_runtime.h>
#include <cuda_bf16.h>
#include <math.h>
#include <stdint.h>

#define PI_D 3.14159265358979323846

// ================= family-safe PTX helpers =================
__device__ __forceinline__ uint32_t smem_u32(const void* p) {
    uint32_t a;
    asm("{ .reg .u64 t; cvta.to.shared.u64 t, %1; cvt.u32.u64 %0, t; }" : "=r"(a) : "l"(p));
    return a;
}
__device__ __forceinline__ void cp_async16(uint32_t dst, const void* src) {
    asm volatile("cp.async.cg.shared.global [%0], [%1], 16;" :: "r"(dst), "l"(src) : "memory");
}
__device__ __forceinline__ void cp_commit() {
    asm volatile("cp.async.commit_group;" ::: "memory");
}
template <int N>
__device__ __forceinline__ void cp_wait() {
    asm volatile("cp.async.wait_group %0;" :: "n"(N) : "memory");
}
__device__ __forceinline__ void ldsm_x4(uint32_t& r0, uint32_t& r1, uint32_t& r2, uint32_t& r3,
                                        uint32_t addr) {
    asm volatile("ldmatrix.sync.aligned.m8n8.x4.shared.b16 {%0,%1,%2,%3}, [%4];"
                 : "=r"(r0), "=r"(r1), "=r"(r2), "=r"(r3) : "r"(addr));
}
__device__ __forceinline__ void mma_bf16(float* c, const uint32_t* a, const uint32_t* b) {
    asm volatile("mma.sync.aligned.m16n8k16.row.col.f32.bf16.bf16.f32 "
                 "{%0,%1,%2,%3}, {%4,%5,%6,%7}, {%8,%9}, {%0,%1,%2,%3};"
                 : "+f"(c[0]), "+f"(c[1]), "+f"(c[2]), "+f"(c[3])
                 : "r"(a[0]), "r"(a[1]), "r"(a[2]), "r"(a[3]), "r"(b[0]), "r"(b[1]));
}

// ================= global scratch =================
__device__ float g_dmat[5 * 19 * 81];

__device__ float g_psi0[32 * 64 * 165];
__device__ float g_psi1[64 * 128 * 165];
__device__ float g_psi2[128 * 128 * 9];
__device__ float g_part[12582912];  // split-K partials: 8*192*8192 = 8*192*4096*2 floats

__device__ __align__(256) __nv_bfloat16 g_Bf_h[4096 * 192];
__device__ __align__(256) __nv_bfloat16 g_Bf_l[4096 * 192];
__device__ __align__(256) __nv_bfloat16 g_Bb_h[192 * 4096];
__device__ __align__(256) __nv_bfloat16 g_Bb_l[192 * 4096];
__device__ __align__(256) __nv_bfloat16 g_y1h[4096 * 192];
__device__ __align__(256) __nv_bfloat16 g_y1l[4096 * 192];
__device__ __align__(256) __nv_bfloat16 g_y2h[8192 * 192];
__device__ __align__(256) __nv_bfloat16 g_y2l[8192 * 192];
__device__ __align__(256) __nv_bfloat16 g_sh[8192 * 4096];
__device__ __align__(256) __nv_bfloat16 g_sl[8192 * 4096];

// per-l GEMM operand arenas
__device__ __align__(256) __nv_bfloat16 g_gAh[675840];
__device__ __align__(256) __nv_bfloat16 g_gAl[675840];
__device__ __align__(256) __nv_bfloat16 g_gBh[1351680];
__device__ __align__(256) __nv_bfloat16 g_gBl[1351680];

// split weight operands
__device__ __align__(256) __nv_bfloat16 g_w0h[393216],  g_w0l[393216];
__device__ __align__(256) __nv_bfloat16 g_w1h[1572864], g_w1l[1572864];
__device__ __align__(256) __nv_bfloat16 g_wlh[524288],  g_wll[524288];
__device__ __align__(256) __nv_bfloat16 g_DKTh[36864],  g_DKTl[36864];
__device__ __align__(256) __nv_bfloat16 g_YSTh[2048],   g_YSTl[2048];

__device__ __forceinline__ void split32(float v, __nv_bfloat16& h, __nv_bfloat16& l) {
    h = __float2bfloat16(v);
    l = __float2bfloat16(v - __bfloat162float(h));
}
__device__ __forceinline__ int off165_of(int l) {
    return (l == 0) ? 0 : (l == 1) ? 1 : (l == 2) ? 10 : (l == 3) ? 35 : 84;
}

// ---------- d(beta) = exp(beta * X0_l): 95 warp jobs ----------
__global__ void k_expm()
{
    __shared__ float ws[16][729];
    const int wid_in = threadIdx.x >> 5;
    const int lane   = threadIdx.x & 31;
    const int w = blockIdx.x * 16 + wid_in;
    if (w >= 95) return;
    const int l = w / 19, bidx = w % 19;
    const int d = 2 * l + 1;

    float* Qre  = ws[wid_in];
    float* Qim  = Qre + 81;
    float* Amat = Qim + 81;
    float* Tre  = Amat + 81;
    float* Tim  = Tre + 81;
    float* Xm   = Tim + 81;
    float* Em   = Xm + 81;
    float* Pm   = Em + 81;
    float* tm   = Pm + 81;

    for (int e = lane; e < 243; e += 32) Qre[e] = 0.f;
    __syncwarp();

    if (lane == 0) {
        const float inv = 0.7071067811865476f;
        for (int m = 1; m <= l; m++) {
            Qre[(l - m) * d + (l + m)] = inv;
            Qim[(l - m) * d + (l - m)] = -inv;
            float sgn = (m & 1) ? -inv : inv;
            Qre[(l + m) * d + (l + m)] = sgn;
            Qim[(l + m) * d + (l - m)] = sgn;
        }
        Qre[l * d + l] = 1.f;
        for (int i2 = 0; i2 < d - 1; i2++) {
            float mm = (float)(-l + i2);
            float c  = 0.5f * sqrtf((float)(l * (l + 1)) - mm * (mm + 1.f));
            Amat[i2 * d + i2 + 1]   =  c;
            Amat[(i2 + 1) * d + i2] = -c;
        }
    }
    __syncwarp();

    for (int e = lane; e < d * d; e += 32) {
        int i = e / d, j = e % d;
        float sr = 0.f, si = 0.f;
        for (int k = 0; k < d; k++) {
            float a = Amat[k * d + j];
            sr += Qre[k * d + i] * a;
            si -= Qim[k * d + i] * a;
        }
        Tre[e] = sr; Tim[e] = si;
    }
    __syncwarp();

    double beta_d = (bidx < 16) ? ((bidx + 0.5) * PI_D / 16.0)
                                : ((double)(bidx - 15) * PI_D / 24.0);
    float beta = (float)beta_d;

    for (int e = lane; e < d * d; e += 32) {
        int i = e / d, j = e % d;
        float s = 0.f;
        for (int k = 0; k < d; k++)
            s += Tre[i * d + k] * Qre[k * d + j] - Tim[i * d + k] * Qim[k * d + j];
        Xm[e] = s * beta;
    }
    __syncwarp();

    float nrm = 0.f;
    for (int i = 0; i < d; i++) {
        float rs = 0.f;
        for (int j = 0; j < d; j++) rs += fabsf(Xm[i * d + j]);
        nrm = fmaxf(nrm, rs);
    }
    int sexp = 0;
    while (nrm > 0.5f) { nrm *= 0.5f; sexp++; }
    float sc = ldexpf(1.f, -sexp);
    for (int e = lane; e < d * d; e += 32) Xm[e] *= sc;
    __syncwarp();

    for (int e = lane; e < d * d; e += 32) {
        int i = e / d, j = e % d;
        Em[e] = Xm[e] + (i == j ? 1.f : 0.f);
        Pm[e] = Xm[e];
    }
    __syncwarp();
    for (int t = 2; t <= 10; t++) {
        float rt = 1.f / (float)t;
        for (int e = lane; e < d * d; e += 32) {
            int i = e / d, j = e % d;
            float s = 0.f;
            for (int k = 0; k < d; k++) s += Pm[i * d + k] * Xm[k * d + j];
            tm[e] = s * rt;
        }
        __syncwarp();
        for (int e = lane; e < d * d; e += 32) { Pm[e] = tm[e]; Em[e] += tm[e]; }
        __syncwarp();
    }
    for (int it = 0; it < sexp; it++) {
        for (int e = lane; e < d * d; e += 32) {
            int i = e / d, j = e % d;
            float s = 0.f;
            for (int k = 0; k < d; k++) s += Em[i * d + k] * Em[k * d + j];
            tm[e] = s;
        }
        __syncwarp();
        for (int e = lane; e < d * d; e += 32) Em[e] = tm[e];
        __syncwarp();
    }
    for (int e = lane; e < d * d; e += 32)
        g_dmat[(l * 19 + bidx) * 81 + e] = Em[e];
}

__device__ __forceinline__ float wig_elem(const float* __restrict__ dm, int l, int d,
                                          int u, int v, float alpha, float gamma)
{
    int mp = u - l, m = v - l;
    int r1, r2 = -1; float c1, c2 = 0.f;
    if (mp == 0) { r1 = l; c1 = 1.f; }
    else {
        int mu = mp > 0 ? mp : -mp;
        float sn, cs; sincosf((float)mu * alpha, &sn, &cs);
        if (mp > 0) { r1 = l + mu; c1 = cs; r2 = l - mu; c2 = -sn; }
        else        { r1 = l - mu; c1 = cs; r2 = l + mu; c2 =  sn; }
    }
    int k1, k2 = -1; float e1, e2 = 0.f;
    if (m == 0) { k1 = l; e1 = 1.f; }
    else {
        int mu = m > 0 ? m : -m;
        float sn, cs; sincosf((float)mu * gamma, &sn, &cs);
        if (m > 0) { k1 = l + mu; e1 = cs; k2 = l - mu; e2 =  sn; }
        else       { k1 = l - mu; e1 = cs; k2 = l + mu; e2 = -sn; }
    }
    float val = c1 * e1 * dm[r1 * d + k1];
    if (k2 >= 0) val += c1 * e2 * dm[r1 * d + k2];
    if (r2 >= 0) {
        val += c2 * e1 * dm[r2 * d + k1];
        if (k2 >= 0) val += c2 * e2 * dm[r2 * d + k2];
    }
    return val;
}

__device__ __forceinline__ void decode_l165(int i, int& l, int& off)
{
    if (i < 1)       { l = 0; off = 0; }
    else if (i < 10) { l = 1; off = 1; }
    else if (i < 35) { l = 2; off = 10; }
    else if (i < 84) { l = 3; off = 35; }
    else             { l = 4; off = 84; }
}

// DK^T split: DKT[i (0..191), k (0..191)] = DK[k,i]/192
__global__ void k_build_DK()
{
    int n = blockIdx.x;
    int i = threadIdx.x;
    float val = 0.f;
    if (i < 165) {
        int ia = n / 24, ib = (n % 24) / 8, ic = n % 8;
        double alpha = ia * (2.0 * PI_D / 8.0);
        double gam   = (-2.0 * PI_D + ic * (4.0 * PI_D / 7.0)) - alpha;
        int l, off; decode_l165(i, l, off);
        int d = 2 * l + 1, r = i - off, u = r / d, v = r % d;
        const float* dm = &g_dmat[(l * 19 + 16 + ib) * 81];
        val = wig_elem(dm, l, d, u, v, (float)alpha, (float)gam)
            * sqrtf(2.f * l + 1.f) * (1.f / 192.f);
    }
    __nv_bfloat16 h, lo;
    split32(val, h, lo);
    g_DKTh[i * 192 + n] = h;
    g_DKTl[i * 192 + n] = lo;
}

// split-bf16 D_ACT operands, smem-staged (one block per (ia, ib))
__global__ void __launch_bounds__(256) k_build_DACT()
{
    __shared__ float sval[16][166];
    const int ia = blockIdx.x >> 4, ib = blockIdx.x & 15;
    const int n0 = blockIdx.x * 16;
    const int tid = threadIdx.x;

    for (int idx = tid; idx < 16 * 165; idx += 256) {
        int ic = idx / 165, i = idx - ic * 165;
        float alpha = (float)(ia * (2.0 * PI_D / 16.0));
        float gam   = (float)(ic * (2.0 * PI_D / 16.0));
        int l, off; decode_l165(i, l, off);
        int d = 2 * l + 1, r = i - off, u = r / d, v = r % d;
        const float* dm = &g_dmat[(l * 19 + ib) * 81];
        sval[ic][i] = wig_elem(dm, l, d, u, v, alpha, gam) * sqrtf(2.f * l + 1.f);
    }
    __syncthreads();

    for (int idx = tid; idx < 16 * 192; idx += 256) {
        int ic = idx / 192, i = idx - ic * 192;
        float v = (i < 165) ? sval[ic][i] : 0.f;
        __nv_bfloat16 h, lo;
        split32(v, h, lo);
        size_t o = (size_t)(n0 + ic) * 192 + i;
        g_Bf_h[o] = h; g_Bf_l[o] = lo;
    }
    float bb = (float)((ib + 0.5) * PI_D / 16.0);
    float qw = sinf(bb) * (float)(0.09801714032956060362 / 256.0); // sin(pi/32)/256
    for (int idx = tid; idx < 192 * 16; idx += 256) {
        int i = idx >> 4, ic = idx & 15;
        float v = (i < 165) ? sval[ic][i] * qw : 0.f;
        __nv_bfloat16 h, lo;
        split32(v, h, lo);
        size_t o = (size_t)i * 4096 + n0 + ic;
        g_Bb_h[o] = h; g_Bb_l[o] = lo;
    }
}

// Y_S2^T split: YST[i (0..63), k (0..31)] = YS2[k, i]/24 (i<9, k<24), else 0
__global__ void k_build_YS2()
{
    __shared__ float sY[24][9];
    int t = threadIdx.x;
    if (t < 216) {
        int p = t / 9, i = t % 9;
        int ia = p / 3, ib = p % 3;
        float alpha = (float)(ia * (2.0 * PI_D / 8.0));
        int l, off;
        if (i < 1)      { l = 0; off = 0; }
        else if (i < 4) { l = 1; off = 1; }
        else            { l = 2; off = 4; }
        int d = 2 * l + 1, u = i - off, mp = u - l;
        const float* dm = &g_dmat[(l * 19 + 16 + ib) * 81];
        float val;
        if (mp == 0) val = dm[l * d + l];
        else {
            int mu = mp > 0 ? mp : -mp;
            float sn, cs; sincosf((float)mu * alpha, &sn, &cs);
            if (mp > 0) val = cs * dm[(l + mu) * d + l] - sn * dm[(l - mu) * d + l];
            else        val = cs * dm[(l - mu) * d + l] + sn * dm[(l + mu) * d + l];
        }
        sY[p][i] = val * sqrtf(2.f * l + 1.f) * (1.f / 24.f);
    }
    __syncthreads();
    for (int idx = t; idx < 64 * 32; idx += blockDim.x) {
        int i = idx >> 5, k = idx & 31;
        float v = (i < 9 && k < 24) ? sY[k][i] : 0.f;
        __nv_bfloat16 h, lo;
        split32(v, h, lo);
        g_YSTh[idx] = h; g_YSTl[idx] = lo;
    }
}

// ---------- elementwise splits ----------
__global__ void k_split(const float* __restrict__ in,
                        __nv_bfloat16* __restrict__ oh, __nv_bfloat16* __restrict__ ol, int n)
{
    int i = blockIdx.x * 256 + threadIdx.x;
    if (i >= n) return;
    __nv_bfloat16 h, lo;
    split32(in[i], h, lo);
    oh[i] = h; ol[i] = lo;
}
__global__ void k_split_pad(const float* __restrict__ in,
                            __nv_bfloat16* __restrict__ oh, __nv_bfloat16* __restrict__ ol,
                            int n)
{
    int i = blockIdx.x * 256 + threadIdx.x;
    if (i >= n) return;
    int r = i >> 5, c = i & 31;
    float v = (c < 24) ? in[r * 24 + c] : 0.f;
    __nv_bfloat16 h, lo;
    split32(v, h, lo);
    oh[i] = h; ol[i] = lo;
}

// ---------- gathers for per-l block-diagonal GEMMs ----------
__global__ void k_gather_A(const float* __restrict__ X,
                           __nv_bfloat16* __restrict__ Ah, __nv_bfloat16* __restrict__ Al,
                           int f_in, int rowlen, int total)
{
    int e = blockIdx.x * 256 + threadIdx.x;
    if (e >= total) return;
    const int sa = 64 * f_in;
    int l, off;
    if      (e < sa * 1)  { l = 0; off = 0; }
    else if (e < sa * 10) { l = 1; off = 1; }
    else if (e < sa * 35) { l = 2; off = 10; }
    else if (e < sa * 84) { l = 3; off = 35; }
    else                  { l = 4; off = 84; }
    const int d = 2 * l + 1;
    const int Kl = f_in * d;
    int local = e - sa * off;
    int r = local / Kl, c = local - r * Kl;
    int b = r / d, m = r - b * d;
    int x = c / d, u = c - x * d;
    float v = X[(size_t)(b * f_in + x) * rowlen + off + u * d + m];
    __nv_bfloat16 h, lo;
    split32(v, h, lo);
    Ah[e] = h; Al[e] = lo;
}

__global__ void k_gather_B(const float* __restrict__ PSI,
                           __nv_bfloat16* __restrict__ Bh, __nv_bfloat16* __restrict__ Bl,
                           int f_in, int f_out, int total)
{
    int e = blockIdx.x * 256 + threadIdx.x;
    if (e >= total) return;
    const int sb = f_in * f_out;
    int l, off;
    if      (e < sb * 1)  { l = 0; off = 0; }
    else if (e < sb * 10) { l = 1; off = 1; }
    else if (e < sb * 35) { l = 2; off = 10; }
    else if (e < sb * 84) { l = 3; off = 35; }
    else                  { l = 4; off = 84; }
    const int d = 2 * l + 1;
    const int Kl = f_in * d;
    int local = e - sb * off;
    int r = local / Kl, c = local - r * Kl;
    int y = r / d, v = r - y * d;
    int x = c / d, u = c - x * d;
    float val = PSI[(size_t)(x * f_out + y) * 165 + off + u * d + v];
    __nv_bfloat16 h, lo;
    split32(val, h, lo);
    Bh[e] = h; Bl[e] = lo;
}

// B for so3->s2: B2[y, (x*d+u)] = psi2[(x*128+y)*9 + offY + u], l in {0,1,2}
__global__ void k_gather_B2(const float* __restrict__ PSI2,
                            __nv_bfloat16* __restrict__ Bh, __nv_bfloat16* __restrict__ Bl,
                            int total)
{
    int e = blockIdx.x * 256 + threadIdx.x;
    if (e >= total) return;
    const int sb = 16384; // 128*128
    int l, offY;
    if      (e < sb * 1) { l = 0; offY = 0; }
    else if (e < sb * 4) { l = 1; offY = 1; }
    else                 { l = 2; offY = 4; }
    const int d = 2 * l + 1;
    const int Kl = 128 * d;
    int local = e - sb * offY;
    int y = local / Kl, c = local - y * Kl;
    int x = c / d, u = c - x * d;
    float val = PSI2[(size_t)(x * 128 + y) * 9 + offY + u];
    __nv_bfloat16 h, lo;
    split32(val, h, lo);
    Bh[e] = h; Bl[e] = lo;
}

__global__ void k_zero_pad(__nv_bfloat16* __restrict__ Yh, __nv_bfloat16* __restrict__ Yl,
                           int rows)
{
    int idx = blockIdx.x * 256 + threadIdx.x;
    int total = rows * 27;
    if (idx >= total) return;
    int r = idx / 27, c = 165 + idx - r * 27;
    __nv_bfloat16 z = __float2bfloat16(0.f);
    Yh[(size_t)r * 192 + c] = z;
    Yl[(size_t)r * 192 + c] = z;
}

// fused split-K reduction + gather_A: sums transposed partials and scatters
// split-bf16 directly into the per-l arena.
// part[(s*192 + c)*M + m]; e = 64*f_in*off + (b*d+mm)*(f_in*d) + x*d + u
__global__ void k_reduce_g(const float* __restrict__ part,
                           __nv_bfloat16* __restrict__ Ah, __nv_bfloat16* __restrict__ Al,
                           int M, int S, int f_in, int cmax)
{
    int idx = blockIdx.x * 256 + threadIdx.x;
    if (idx >= M * 165) return;
    int m = idx & (M - 1);
    int c = idx >> (M == 4096 ? 12 : 13);
    if (c >= cmax) return;
    float acc = 0.f;
    for (int s = 0; s < S; s++)
        acc += part[((size_t)s * 192 + c) * M + m];
    int l, off; decode_l165(c, l, off);
    int d = 2 * l + 1;
    int u = (c - off) / d, mm = (c - off) - u * d;
    int b = m / f_in, x = m - b * f_in;
    size_t e = (size_t)64 * f_in * off + (size_t)(b * d + mm) * (f_in * d) + x * d + u;
    __nv_bfloat16 h, lo;
    split32(acc, h, lo);
    Ah[e] = h; Al[e] = lo;
}

// ---------- shared HMMA split-bf16 mainloop ----------
template <int BM, int BN, int WM, int WN>
__device__ __forceinline__ void mma_mainloop(
    const __nv_bfloat16* __restrict__ Ahi, const __nv_bfloat16* __restrict__ Alo,
    const __nv_bfloat16* __restrict__ Bhi, const __nv_bfloat16* __restrict__ Blo,
    int row0, int n0, int lda, int Kloop, char* smem,
    float acc[WM / 16][WN / 8][4])
{
    constexpr int MT = WM / 16, NT = WN / 8;
    constexpr int SA = BM * 80, SB = BN * 80;
    constexpr int SS = 2 * SA + 2 * SB;
    const uint32_t sbase = smem_u32(smem);
    const int tid  = threadIdx.x;
    const int lane = tid & 31, wid = tid >> 5;
    const int m_warp = (wid >> 2) * WM, n_warp = (wid & 3) * WN;
    const int NKB = Kloop >> 5;

    auto load_stage = [&](int kb, int s) {
        const uint32_t sbs = sbase + s * SS;
#pragma unroll
        for (int i = tid; i < BM * 8; i += 256) {
            int mtx = (i >= BM * 4);
            int j = i - mtx * (BM * 4);
            int r = j >> 2, c = j & 3;
            const __nv_bfloat16* src = (mtx ? Alo : Ahi)
                + (size_t)(row0 + r) * lda + kb * 32 + c * 8;
            cp_async16(sbs + mtx * SA + r * 80 + c * 16, src);
        }
#pragma unroll
        for (int i = tid; i < BN * 8; i += 256) {
            int mtx = (i >= BN * 4);
            int j = i - mtx * (BN * 4);
            int r = j >> 2, c = j & 3;
            const __nv_bfloat16* src = (mtx ? Blo : Bhi)
                + (size_t)(n0 + r) * lda + kb * 32 + c * 8;
            cp_async16(sbs + 2 * SA + mtx * SB + r * 80 + c * 16, src);
        }
    };

    load_stage(0, 0); cp_commit();
    if (NKB > 1) load_stage(1, 1);
    cp_commit();

    const int a_roff = (lane & 7) + ((lane >> 3) & 1) * 8;
    const int a_coff = ((lane >> 4) & 1) * 8;
    const int b_roff = (lane & 7) + ((lane >> 4) & 1) * 8;
    const int b_coff = ((lane >> 3) & 1) * 8;

    for (int kb = 0; kb < NKB; kb++) {
        if (kb + 1 < NKB) cp_wait<1>(); else cp_wait<0>();
        __syncthreads();
        const uint32_t sbs = sbase + (kb & 1) * SS;
#pragma unroll
        for (int kk = 0; kk < 2; kk++) {
            uint32_t bh[NT][2], bl[NT][2];
#pragma unroll
            for (int n2 = 0; n2 < NT / 2; n2++) {
                uint32_t ab = sbs + 2 * SA
                    + (n_warp + n2 * 16 + b_roff) * 80 + (kk * 16 + b_coff) * 2;
                ldsm_x4(bh[2 * n2][0], bh[2 * n2][1], bh[2 * n2 + 1][0], bh[2 * n2 + 1][1], ab);
                ldsm_x4(bl[2 * n2][0], bl[2 * n2][1], bl[2 * n2 + 1][0], bl[2 * n2 + 1][1],
                        ab + SB);
            }
            uint32_t af[MT][4];
#pragma unroll
            for (int mt = 0; mt < MT; mt++) {
                uint32_t aa = sbs + (m_warp + mt * 16 + a_roff) * 80 + (kk * 16 + a_coff) * 2;
                ldsm_x4(af[mt][0], af[mt][1], af[mt][2], af[mt][3], aa);
            }
#pragma unroll
            for (int mt = 0; mt < MT; mt++)
#pragma unroll
                for (int nt = 0; nt < NT; nt++) mma_bf16(acc[mt][nt], af[mt], bh[nt]);
#pragma unroll
            for (int mt = 0; mt < MT; mt++)
#pragma unroll
                for (int nt = 0; nt < NT; nt++) mma_bf16(acc[mt][nt], af[mt], bl[nt]);
#pragma unroll
            for (int mt = 0; mt < MT; mt++) {
                uint32_t aa = sbs + SA
                    + (m_warp + mt * 16 + a_roff) * 80 + (kk * 16 + a_coff) * 2;
                ldsm_x4(af[mt][0], af[mt][1], af[mt][2], af[mt][3], aa);
            }
#pragma unroll
            for (int mt = 0; mt < MT; mt++)
#pragma unroll
                for (int nt = 0; nt < NT; nt++) mma_bf16(acc[mt][nt], af[mt], bh[nt]);
        }
        __syncthreads();
        if (kb + 2 < NKB) load_stage(kb + 2, kb & 1);
        cp_commit();
    }
    cp_wait<0>();
    __syncthreads();
}

// ---------- fwd act GEMM: relu + split-bf16 store ----------
__global__ void __launch_bounds__(256)
k_mma_relu(const __nv_bfloat16* __restrict__ Ahi, const __nv_bfloat16* __restrict__ Alo,
           const __nv_bfloat16* __restrict__ Bhi, const __nv_bfloat16* __restrict__ Blo,
           __nv_bfloat16* __restrict__ Chi, __nv_bfloat16* __restrict__ Clo, int K)
{
    constexpr int BM = 128, BN = 128, WM = 64, WN = 32, MT = 4, NT = 4;
    extern __shared__ char smem[];
    const int tid = threadIdx.x, lane = tid & 31, wid = tid >> 5;
    const int m_warp = (wid >> 2) * WM, n_warp = (wid & 3) * WN;
    const int row0 = blockIdx.y * BM, n0 = blockIdx.x * BN;
    float acc[MT][NT][4];
#pragma unroll
    for (int i = 0; i < MT; i++)
#pragma unroll
        for (int j = 0; j < NT; j++)
#pragma unroll
            for (int q = 0; q < 4; q++) acc[i][j][q] = 0.f;

    mma_mainloop<BM, BN, WM, WN>(Ahi, Alo, Bhi, Blo, row0, n0, K, K, smem, acc);

    const int qr = lane >> 2, qc = lane & 3;
    constexpr int LDS = BN + 8;
    __nv_bfloat16* sC = (__nv_bfloat16*)smem;
#pragma unroll
    for (int mt = 0; mt < MT; mt++)
#pragma unroll
        for (int nt = 0; nt < NT; nt++)
#pragma unroll
            for (int i = 0; i < 2; i++) {
                int r = m_warp + mt * 16 + qr + i * 8;
                int c = n_warp + nt * 8 + qc * 2;
                float v0 = acc[mt][nt][2 * i];
                float v1 = acc[mt][nt][2 * i + 1];
                v0 = v0 > 0.f ? v0 * 1.4142135623730951f : 0.f;
                v1 = v1 > 0.f ? v1 * 1.4142135623730951f : 0.f;
                __nv_bfloat162 hp;
                hp.x = __float2bfloat16(v0);
                hp.y = __float2bfloat16(v1);
                *(__nv_bfloat162*)&sC[r * LDS + c] = hp;
                acc[mt][nt][2 * i]     = v0 - __bfloat162float(hp.x);
                acc[mt][nt][2 * i + 1] = v1 - __bfloat162float(hp.y);
            }
    __syncthreads();
#pragma unroll
    for (int it = 0; it < BM * BN / 8 / 256; it++) {
        int idx = it * 256 + tid;
        int r = idx / (BN / 8), c8 = idx % (BN / 8);
        *(uint4*)&Chi[(size_t)(row0 + r) * 4096 + n0 + c8 * 8] = *(uint4*)&sC[r * LDS + c8 * 8];
    }
    __syncthreads();
#pragma unroll
    for (int mt = 0; mt < MT; mt++)
#pragma unroll
        for (int nt = 0; nt < NT; nt++)
#pragma unroll
            for (int i = 0; i < 2; i++) {
                int r = m_warp + mt * 16 + qr + i * 8;
                int c = n_warp + nt * 8 + qc * 2;
                __nv_bfloat162 lp;
                lp.x = __float2bfloat16(acc[mt][nt][2 * i]);
                lp.y = __float2bfloat16(acc[mt][nt][2 * i + 1]);
                *(__nv_bfloat162*)&sC[r * LDS + c] = lp;
            }
    __syncthreads();
#pragma unroll
    for (int it = 0; it < BM * BN / 8 / 256; it++) {
        int idx = it * 256 + tid;
        int r = idx / (BN / 8), c8 = idx % (BN / 8);
        *(uint4*)&Clo[(size_t)(row0 + r) * 4096 + n0 + c8 * 8] = *(uint4*)&sC[r * LDS + c8 * 8];
    }
}

// ---------- fp32-output GEMM (psi projections; 64x64) ----------
__global__ void __launch_bounds__(256)
k_mma_f32(const __nv_bfloat16* __restrict__ Ahi, const __nv_bfloat16* __restrict__ Alo,
          const __nv_bfloat16* __restrict__ Bhi, const __nv_bfloat16* __restrict__ Blo,
          float* __restrict__ Cf, int K, int ldc, int ncol)
{
    constexpr int BM = 64, BN = 64, WM = 32, WN = 16, MT = 2, NT = 2;
    extern __shared__ char smem[];
    const int tid = threadIdx.x, lane = tid & 31, wid = tid >> 5;
    const int m_warp = (wid >> 2) * WM, n_warp = (wid & 3) * WN;
    const int row0 = blockIdx.y * BM, n0 = blockIdx.x * BN;
    float acc[MT][NT][4];
#pragma unroll
    for (int i = 0; i < MT; i++)
#pragma unroll
        for (int j = 0; j < NT; j++)
#pragma unroll
            for (int q = 0; q < 4; q++) acc[i][j][q] = 0.f;

    mma_mainloop<BM, BN, WM, WN>(Ahi, Alo, Bhi, Blo, row0, n0, K, K, smem, acc);

    const int qr = lane >> 2, qc = lane & 3;
#pragma unroll
    for (int mt = 0; mt < MT; mt++)
#pragma unroll
        for (int nt = 0; nt < NT; nt++)
#pragma unroll
            for (int i = 0; i < 2; i++) {
                int r = row0 + m_warp + mt * 16 + qr + i * 8;
                int c = n0 + n_warp + nt * 8 + qc * 2;
                if (c < ncol)     Cf[(size_t)r * ldc + c]     = acc[mt][nt][2 * i];
                if (c + 1 < ncol) Cf[(size_t)r * ldc + c + 1] = acc[mt][nt][2 * i + 1];
            }
}

// ---------- transposed split-K bwd GEMM: Cpart[s][192][M] = Bb x s^T chunk ----------
// A = Bb [192, lda], B = s [Mtot, lda]. Tile 64x128, warps 2x4 (32x32 each).
__global__ void __launch_bounds__(256)
k_mma_f32t(const __nv_bfloat16* __restrict__ Ahi, const __nv_bfloat16* __restrict__ Alo,
           const __nv_bfloat16* __restrict__ Bhi, const __nv_bfloat16* __restrict__ Blo,
           float* __restrict__ Cpart, int lda, int Klen, int Mtot)
{
    constexpr int BM = 64, BN = 128, WM = 32, WN = 32, MT = 2, NT = 4;
    extern __shared__ char smem[];
    const int tid = threadIdx.x, lane = tid & 31, wid = tid >> 5;
    const int m_warp = (wid >> 2) * WM, n_warp = (wid & 3) * WN;
    const int row0 = blockIdx.y * BM, n0 = blockIdx.x * BN;
    const int s = blockIdx.z;
    const int k0 = s * Klen;
    float acc[MT][NT][4];
#pragma unroll
    for (int i = 0; i < MT; i++)
#pragma unroll
        for (int j = 0; j < NT; j++)
#pragma unroll
            for (int q = 0; q < 4; q++) acc[i][j][q] = 0.f;

    mma_mainloop<BM, BN, WM, WN>(Ahi + k0, Alo + k0, Bhi + k0, Blo + k0,
                                 row0, n0, lda, Klen, smem, acc);

    float* outp = Cpart + (size_t)s * 192 * Mtot;
    const int qr = lane >> 2, qc = lane & 3;
#pragma unroll
    for (int mt = 0; mt < MT; mt++)
#pragma unroll
        for (int nt = 0; nt < NT; nt++)
#pragma unroll
            for (int i = 0; i < 2; i++) {
                int rC = row0 + m_warp + mt * 16 + qr + i * 8;
                int cM = n0 + n_warp + nt * 8 + qc * 2;
                outp[(size_t)rC * Mtot + cM]     = acc[mt][nt][2 * i];
                outp[(size_t)rC * Mtot + cM + 1] = acc[mt][nt][2 * i + 1];
            }
}

// ---------- merged per-l so3_linear GEMM ----------
__global__ void __launch_bounds__(256)
k_mma_so3(const __nv_bfloat16* __restrict__ gAh, const __nv_bfloat16* __restrict__ gAl,
          const __nv_bfloat16* __restrict__ gBh, const __nv_bfloat16* __restrict__ gBl,
          __nv_bfloat16* __restrict__ Yh, __nv_bfloat16* __restrict__ Yl,
          int f_in, int f_out)
{
    constexpr int BM = 64, BN = 64, WM = 32, WN = 16, MT = 2, NT = 2;
    const int l = blockIdx.z;
    const int d = 2 * l + 1;
    const int off = off165_of(l);
    const int M = 64 * d, N = f_out * d, K = f_in * d;
    if ((int)blockIdx.x * BN >= N || (int)blockIdx.y * BM >= M) return;

    extern __shared__ char smem[];
    const int tid = threadIdx.x, lane = tid & 31, wid = tid >> 5;
    const int m_warp = (wid >> 2) * WM, n_warp = (wid & 3) * WN;
    const int row0 = blockIdx.y * BM, n0 = blockIdx.x * BN;
    const size_t oA = (size_t)64 * f_in * off;
    const size_t oB = (size_t)f_in * f_out * off;
    float acc[MT][NT][4];
#pragma unroll
    for (int i = 0; i < MT; i++)
#pragma unroll
        for (int j = 0; j < NT; j++)
#pragma unroll
            for (int q = 0; q < 4; q++) acc[i][j][q] = 0.f;

    mma_mainloop<BM, BN, WM, WN>(gAh + oA, gAl + oA, gBh + oB, gBl + oB,
                                 row0, n0, K, K, smem, acc);

    const float scale = rsqrtf((float)(f_in * d));
    const int qr = lane >> 2, qc = lane & 3;
#pragma unroll
    for (int mt = 0; mt < MT; mt++)
#pragma unroll
        for (int nt = 0; nt < NT; nt++)
#pragma unroll
            for (int i = 0; i < 2; i++) {
                int r = row0 + m_warp + mt * 16 + qr + i * 8;
                int b = r / d, m = r - b * d;
#pragma unroll
                for (int jj = 0; jj < 2; jj++) {
                    int c = n0 + n_warp + nt * 8 + qc * 2 + jj;
                    int y = c / d, v = c - y * d;
                    float val = acc[mt][nt][2 * i + jj] * scale;
                    __nv_bfloat16 h, lo;
                    split32(val, h, lo);
                    size_t o = (size_t)(b * f_out + y) * 192 + off + v * d + m;
                    Yh[o] = h; Yl[o] = lo;
                }
            }
}

// ---------- merged per-l so3 -> s2 GEMM (fp32 scatter to output) ----------
__global__ void __launch_bounds__(256)
k_mma_s2(const __nv_bfloat16* __restrict__ gAh, const __nv_bfloat16* __restrict__ gAl,
         const __nv_bfloat16* __restrict__ gBh, const __nv_bfloat16* __restrict__ gBl,
         float* __restrict__ O)
{
    constexpr int BM = 64, BN = 64, WM = 32, WN = 16, MT = 2, NT = 2;
    const int l = blockIdx.z;
    const int d = 2 * l + 1;
    const int offY = l * l;
    const int offA = (l == 0) ? 0 : (l == 1) ? 1 : 10;
    const int M = 64 * d, K = 128 * d;
    if ((int)blockIdx.y * BM >= M) return;

    extern __shared__ char smem[];
    const int tid = threadIdx.x, lane = tid & 31, wid = tid >> 5;
    const int m_warp = (wid >> 2) * WM, n_warp = (wid & 3) * WN;
    const int row0 = blockIdx.y * BM, n0 = blockIdx.x * BN;
    const size_t oA = (size_t)8192 * offA;
    const size_t oB = (size_t)16384 * offY;
    float acc[MT][NT][4];
#pragma unroll
    for (int i = 0; i < MT; i++)
#pragma unroll
        for (int j = 0; j < NT; j++)
#pragma unroll
            for (int q = 0; q < 4; q++) acc[i][j][q] = 0.f;

    mma_mainloop<BM, BN, WM, WN>(gAh + oA, gAl + oA, gBh + oB, gBl + oB,
                                 row0, n0, K, K, smem, acc);

    const float scale = rsqrtf(128.f * (float)d);
    const int qr = lane >> 2, qc = lane & 3;
#pragma unroll
    for (int mt = 0; mt < MT; mt++)
#pragma unroll
        for (int nt = 0; nt < NT; nt++)
#pragma unroll
            for (int i = 0; i < 2; i++) {
                int r = row0 + m_warp + mt * 16 + qr + i * 8;
                int b = r / d, m = r - b * d;
#pragma unroll
                for (int jj = 0; jj < 2; jj++) {
                    int y = n0 + n_warp + nt * 8 + qc * 2 + jj;
                    O[(size_t)(b * 128 + y) * 9 + offY + m] =
                        acc[mt][nt][2 * i + jj] * scale;
                }
            }
}

// ---------- launch ----------
extern "C" void kernel_launch(void* const* d_in, const int* in_sizes, int n_in,
                              void* d_out, int out_size)
{
    const float* x    = (const float*)d_in[0];
    const float* w0   = (const float*)d_in[1];
    const float* w1   = (const float*)d_in[2];
    const float* wlin = (const float*)d_in[3];
    float* out = (float*)d_out;

    float *psi0, *psi1, *psi2, *part;
    __nv_bfloat16 *Bfh, *Bfl, *Bbh, *Bbl, *y1h, *y1l, *y2h, *y2l, *sh, *sl;
    __nv_bfloat16 *gAh, *gAl, *gBh, *gBl;
    __nv_bfloat16 *w0h, *w0l, *w1h, *w1l, *wlh, *wll, *DKTh, *DKTl, *YSTh, *YSTl;
    cudaGetSymbolAddress((void**)&psi0, g_psi0);
    cudaGetSymbolAddress((void**)&psi1, g_psi1);
    cudaGetSymbolAddress((void**)&psi2, g_psi2);
    cudaGetSymbolAddress((void**)&part, g_part);
    cudaGetSymbolAddress((void**)&Bfh, g_Bf_h);
    cudaGetSymbolAddress((void**)&Bfl, g_Bf_l);
    cudaGetSymbolAddress((void**)&Bbh, g_Bb_h);
    cudaGetSymbolAddress((void**)&Bbl, g_Bb_l);
    cudaGetSymbolAddress((void**)&y1h, g_y1h);
    cudaGetSymbolAddress((void**)&y1l, g_y1l);
    cudaGetSymbolAddress((void**)&y2h, g_y2h);
    cudaGetSymbolAddress((void**)&y2l, g_y2l);
    cudaGetSymbolAddress((void**)&sh, g_sh);
    cudaGetSymbolAddress((void**)&sl, g_sl);
    cudaGetSymbolAddress((void**)&gAh, g_gAh);
    cudaGetSymbolAddress((void**)&gAl, g_gAl);
    cudaGetSymbolAddress((void**)&gBh, g_gBh);
    cudaGetSymbolAddress((void**)&gBl, g_gBl);
    cudaGetSymbolAddress((void**)&w0h, g_w0h);
    cudaGetSymbolAddress((void**)&w0l, g_w0l);
    cudaGetSymbolAddress((void**)&w1h, g_w1h);
    cudaGetSymbolAddress((void**)&w1l, g_w1l);
    cudaGetSymbolAddress((void**)&wlh, g_wlh);
    cudaGetSymbolAddress((void**)&wll, g_wll);
    cudaGetSymbolAddress((void**)&DKTh, g_DKTh);
    cudaGetSymbolAddress((void**)&DKTl, g_DKTl);
    cudaGetSymbolAddress((void**)&YSTh, g_YSTh);
    cudaGetSymbolAddress((void**)&YSTl, g_YSTl);

    constexpr int SMEMF = 2 * (2 * 128 * 80 + 2 * 128 * 80);  // 81920
    constexpr int SMEMB = 2 * (2 * 64 * 80 + 2 * 64 * 80);    // 40960
    constexpr int SMEMT = 2 * (2 * 64 * 80 + 2 * 128 * 80);   // 61440
    cudaFuncSetAttribute((const void*)k_mma_relu,
                         cudaFuncAttributeMaxDynamicSharedMemorySize, SMEMF);
    cudaFuncSetAttribute((const void*)k_mma_f32t,
                         cudaFuncAttributeMaxDynamicSharedMemorySize, SMEMT);

    // constants + psi (slot 5 = launch index 3 -> psi1 64x64 reference kernel)
    k_expm<<<6, 512>>>();                                                   // 0
    k_build_DK<<<192, 192>>>();                                             // 1
    k_split<<<(1572864 + 255) / 256, 256>>>(w1, w1h, w1l, 1572864);         // 2
    k_mma_f32<<<dim3(3, 128), 256, SMEMB>>>(w1h, w1l, DKTh, DKTl,
                                            psi1, 192, 165, 165);           // 3 <- profiled
    k_build_DACT<<<256, 256>>>();                                           // 4
    k_split<<<(393216 + 255) / 256, 256>>>(w0, w0h, w0l, 393216);           // 5
    k_mma_f32<<<dim3(3, 32), 256, SMEMB>>>(w0h, w0l, DKTh, DKTl,
                                           psi0, 192, 165, 165);            // 6
    k_build_YS2<<<1, 256>>>();                                              // 7
    k_split_pad<<<(524288 + 255) / 256, 256>>>(wlin, wlh, wll, 524288);     // 8
    k_mma_f32<<<dim3(1, 256), 256, SMEMB>>>(wlh, wll, YSTh, YSTl,
                                            psi2, 32, 9, 9);                // 9

    // ---- layer 0 ----
    k_gather_A<<<(2048 * 165 + 255) / 256, 256>>>(x, gAh, gAl, 32, 455, 2048 * 165);
    k_gather_B<<<(2048 * 165 + 255) / 256, 256>>>(psi0, gBh, gBl, 32, 64, 2048 * 165);
    k_mma_so3<<<dim3(9, 9, 5), 256, SMEMB>>>(gAh, gAl, gBh, gBl, y1h, y1l, 32, 64);
    k_zero_pad<<<(4096 * 27 + 255) / 256, 256>>>(y1h, y1l, 4096);
    k_mma_relu<<<dim3(32, 32), 256, SMEMF>>>(y1h, y1l, Bfh, Bfl, sh, sl, 192);
    // bwd0: split-K 8 x 512 -> 768 CTAs; fused reduce+gather (needs all 165 rows)
    k_mma_f32t<<<dim3(32, 3, 8), 256, SMEMT>>>(Bbh, Bbl, sh, sl, part, 4096, 512, 4096);
    k_reduce_g<<<(4096 * 165 + 255) / 256, 256>>>(part, gAh, gAl, 4096, 8, 64, 165);

    // ---- layer 1 ----
    k_gather_B<<<(8192 * 165 + 255) / 256, 256>>>(psi1, gBh, gBl, 64, 128, 8192 * 165);
    k_mma_so3<<<dim3(18, 9, 5), 256, SMEMB>>>(gAh, gAl, gBh, gBl, y2h, y2l, 64, 128);
    k_zero_pad<<<(8192 * 27 + 255) / 256, 256>>>(y2h, y2l, 8192);
    k_mma_relu<<<dim3(32, 64), 256, SMEMF>>>(y2h, y2l, Bfh, Bfl, sh, sl, 192);
    // bwd1: consumer (s2 layer) only reads rows c<35 -> compute rows 0..63 only
    // (grid y = 1 instead of 3: cuts the largest GEMM by 3x). Split-K 8 x 512.
    k_mma_f32t<<<dim3(64, 1, 8), 256, SMEMT>>>(Bbh, Bbl, sh, sl, part, 4096, 512, 8192);
    k_reduce_g<<<(8192 * 165 + 255) / 256, 256>>>(part, gAh, gAl, 8192, 8, 128, 35);

    // ---- final so3 -> s2 ----
    k_gather_B2<<<(16384 * 9 + 255) / 256, 256>>>(psi2, gBh, gBl, 16384 * 9);
    k_mma_s2<<<dim3(2, 5, 3), 256, SMEMB>>>(gAh, gAl, gBh, gBl, out);
}